// round 2
// baseline (speedup 1.0000x reference)
#include <cuda_runtime.h>
#include <cuda_fp16.h>
#include <cstdint>

#define D_    1024
#define E_    8
#define DF_   4096
#define TMAX  4096
#define BM    128
#define BN    128
#define BK    32
#define SKEW  8

// ---------------- scratch (device globals; no runtime allocation) ----------
__device__ int    g_cnt[E_];
__device__ int    g_off[E_];
__device__ int    g_tok[E_ * TMAX];
__device__ float  g_w  [E_ * TMAX];
__device__ __half g_xh [(size_t)TMAX * D_];                  // LN output, fp16 (8MB)
__device__ __half g_h  [(size_t)2 * TMAX * DF_];             // expert hidden, compact (64MB)

// ---------------- mma helpers ---------------------------------------------
__device__ __forceinline__ uint32_t smem_u32(const void* p) {
    return (uint32_t)__cvta_generic_to_shared(p);
}
__device__ __forceinline__ void ldm_x4(uint32_t* r, uint32_t a) {
    asm volatile("ldmatrix.sync.aligned.m8n8.x4.shared.b16 {%0,%1,%2,%3}, [%4];\n"
                 : "=r"(r[0]), "=r"(r[1]), "=r"(r[2]), "=r"(r[3]) : "r"(a));
}
__device__ __forceinline__ void ldm_x2(uint32_t* r, uint32_t a) {
    asm volatile("ldmatrix.sync.aligned.m8n8.x2.shared.b16 {%0,%1}, [%2];\n"
                 : "=r"(r[0]), "=r"(r[1]) : "r"(a));
}
__device__ __forceinline__ void mma16816(float* c, const uint32_t* a, const uint32_t* b) {
    asm volatile(
        "mma.sync.aligned.m16n8k16.row.col.f32.f16.f16.f32 "
        "{%0,%1,%2,%3}, {%4,%5,%6,%7}, {%8,%9}, {%0,%1,%2,%3};\n"
        : "+f"(c[0]), "+f"(c[1]), "+f"(c[2]), "+f"(c[3])
        : "r"(a[0]), "r"(a[1]), "r"(a[2]), "r"(a[3]), "r"(b[0]), "r"(b[1]));
}

__device__ __forceinline__ float gelu_exact(float v) {
    return 0.5f * v * (1.0f + erff(v * 0.70710678118654752440f));
}

// Shared compute for a BMxBNxBK smem tile. Warps: 2(M) x 4(N); each warp 64x32.
#define COMPUTE_TILE()                                                           \
    do {                                                                         \
        _Pragma("unroll")                                                        \
        for (int ks = 0; ks < 2; ++ks) {                                         \
            uint32_t af[4][4];                                                   \
            uint32_t bf[4][2];                                                   \
            _Pragma("unroll")                                                    \
            for (int mt = 0; mt < 4; ++mt) {                                     \
                uint32_t ad = smem_u32(                                          \
                    &As[warp_m * 64 + mt * 16 + (lane & 15)]                     \
                       [ks * 16 + (lane >> 4) * 8]);                             \
                ldm_x4(af[mt], ad);                                              \
            }                                                                    \
            _Pragma("unroll")                                                    \
            for (int nt = 0; nt < 4; ++nt) {                                     \
                uint32_t bd = smem_u32(                                          \
                    &Bs[warp_n * 32 + nt * 8 + (lane & 7)]                       \
                       [ks * 16 + ((lane >> 3) & 1) * 8]);                       \
                ldm_x2(bf[nt], bd);                                              \
            }                                                                    \
            _Pragma("unroll")                                                    \
            for (int mt = 0; mt < 4; ++mt)                                       \
                _Pragma("unroll")                                                \
                for (int nt = 0; nt < 4; ++nt)                                   \
                    mma16816(acc[mt][nt], af[mt], bf[nt]);                       \
        }                                                                        \
    } while (0)

// ---------------- kernel 0: reset dispatch counters -----------------------
__global__ void reset_kernel() {
    if (threadIdx.x < E_) g_cnt[threadIdx.x] = 0;
}

// ---------------- kernel 0b: exclusive prefix sum of counts ---------------
__global__ void offsets_kernel() {
    if (threadIdx.x == 0) {
        int o = 0;
#pragma unroll
        for (int e = 0; e < E_; ++e) { g_off[e] = o; o += g_cnt[e]; }
    }
}

// ---------------- kernel 1: LayerNorm + router + dispatch -----------------
__global__ __launch_bounds__(256) void ln_gate_kernel(
    const float* __restrict__ x, const float* __restrict__ gamma,
    const float* __restrict__ beta, const float* __restrict__ Wg,
    const float* __restrict__ bg, float* __restrict__ out) {
    const int t   = blockIdx.x;
    const int tid = threadIdx.x;
    const int lane = tid & 31, warp = tid >> 5;

    __shared__ float red[2][8];
    __shared__ float ared[E_][8];
    __shared__ float logits[E_];

    const float4 v = reinterpret_cast<const float4*>(x + (size_t)t * D_)[tid];
    float s  = v.x + v.y + v.z + v.w;
    float ss = v.x * v.x + v.y * v.y + v.z * v.z + v.w * v.w;
#pragma unroll
    for (int o = 16; o > 0; o >>= 1) {
        s  += __shfl_down_sync(0xffffffffu, s, o);
        ss += __shfl_down_sync(0xffffffffu, ss, o);
    }
    if (lane == 0) { red[0][warp] = s; red[1][warp] = ss; }
    __syncthreads();
    if (warp == 0) {
        float a = (lane < 8) ? red[0][lane] : 0.f;
        float b = (lane < 8) ? red[1][lane] : 0.f;
#pragma unroll
        for (int o = 4; o > 0; o >>= 1) {
            a += __shfl_down_sync(0xffffffffu, a, o);
            b += __shfl_down_sync(0xffffffffu, b, o);
        }
        if (lane == 0) { red[0][0] = a; red[1][0] = b; }
    }
    __syncthreads();
    const float mu   = red[0][0] * (1.0f / D_);
    const float var  = red[1][0] * (1.0f / D_) - mu * mu;
    const float rstd = rsqrtf(var + 1e-5f);

    const float4 g  = reinterpret_cast<const float4*>(gamma)[tid];
    const float4 be = reinterpret_cast<const float4*>(beta)[tid];
    const float xn0 = (v.x - mu) * rstd * g.x + be.x;
    const float xn1 = (v.y - mu) * rstd * g.y + be.y;
    const float xn2 = (v.z - mu) * rstd * g.z + be.z;
    const float xn3 = (v.w - mu) * rstd * g.w + be.w;

    // residual init: out = x (expert contributions atomically added later)
    reinterpret_cast<float4*>(out + (size_t)t * D_)[tid] = v;
    __half2* xh2 = reinterpret_cast<__half2*>(g_xh + (size_t)t * D_);
    xh2[tid * 2 + 0] = __floats2half2_rn(xn0, xn1);
    xh2[tid * 2 + 1] = __floats2half2_rn(xn2, xn3);

    // router logits (fp32)
    float acc[E_];
#pragma unroll
    for (int e = 0; e < E_; ++e) {
        const float4 w = reinterpret_cast<const float4*>(Wg + (size_t)e * D_)[tid];
        acc[e] = xn0 * w.x + xn1 * w.y + xn2 * w.z + xn3 * w.w;
    }
#pragma unroll
    for (int e = 0; e < E_; ++e) {
        float a = acc[e];
#pragma unroll
        for (int o = 16; o > 0; o >>= 1) a += __shfl_down_sync(0xffffffffu, a, o);
        if (lane == 0) ared[e][warp] = a;
    }
    __syncthreads();
    if (tid < E_) {
        float a = 0.f;
#pragma unroll
        for (int w = 0; w < 8; ++w) a += ared[tid][w];
        logits[tid] = a + bg[tid];
    }
    __syncthreads();
    if (tid == 0) {
        float m = logits[0];
#pragma unroll
        for (int e = 1; e < E_; ++e) m = fmaxf(m, logits[e]);
        float p[E_], Z = 0.f;
#pragma unroll
        for (int e = 0; e < E_; ++e) { p[e] = expf(logits[e] - m); Z += p[e]; }
        int i1 = 0;
#pragma unroll
        for (int e = 1; e < E_; ++e) if (p[e] > p[i1]) i1 = e;
        int i2 = (i1 == 0) ? 1 : 0;
#pragma unroll
        for (int e = 0; e < E_; ++e) if (e != i1 && p[e] > p[i2]) i2 = e;
        const float p1 = p[i1] / Z, p2 = p[i2] / Z;
        const float dn = p1 + p2 + 1e-8f;
        const float w1 = p1 / dn, w2 = p2 / dn;
        int pos1 = atomicAdd(&g_cnt[i1], 1);
        g_tok[i1 * TMAX + pos1] = t; g_w[i1 * TMAX + pos1] = w1;
        int pos2 = atomicAdd(&g_cnt[i2], 1);
        g_tok[i2 * TMAX + pos2] = t; g_w[i2 * TMAX + pos2] = w2;
    }
}

// ---------------- kernel 2: H = gelu(Xe @ W1e^T + b1) ----------------------
__global__ __launch_bounds__(256) void gemm1_kernel(
    const float* __restrict__ W1, const float* __restrict__ b1) {
    const int e  = blockIdx.z;
    const int M  = g_cnt[e];
    const int m0 = blockIdx.x * BM;
    if (m0 >= M) return;
    const int n0  = blockIdx.y * BN;
    const int hb  = g_off[e];                     // compact H row base

    __shared__ __half As[BM][BK + SKEW];
    __shared__ __half Bs[BN][BK + SKEW];

    const int tid = threadIdx.x;
    const int lane = tid & 31, wid = tid >> 5;
    const int warp_m = wid >> 2, warp_n = wid & 3;

    const int lr = tid >> 1;
    const int lc = (tid & 1) * 16;
    const int rg = m0 + lr;
    const bool rowok = (rg < M);
    const __half* aptr = nullptr;
    if (rowok) {
        const int tok = g_tok[e * TMAX + rg];
        aptr = g_xh + (size_t)tok * D_ + lc;
    }
    const float* bptr = W1 + ((size_t)e * DF_ + n0 + lr) * D_ + lc;

    float acc[4][4][4];
#pragma unroll
    for (int i = 0; i < 4; ++i)
#pragma unroll
        for (int j = 0; j < 4; ++j)
#pragma unroll
            for (int k = 0; k < 4; ++k) acc[i][j][k] = 0.f;

    uint4 aS[2]; float4 bS[4];
    auto fetch = [&](int k0) {
        if (rowok) {
            aS[0] = *(const uint4*)(aptr + k0);
            aS[1] = *(const uint4*)(aptr + k0 + 8);
        } else {
            aS[0] = make_uint4(0, 0, 0, 0);
            aS[1] = make_uint4(0, 0, 0, 0);
        }
#pragma unroll
        for (int i = 0; i < 4; ++i) bS[i] = *(const float4*)(bptr + k0 + i * 4);
    };
    auto stage = [&]() {
        *(uint4*)&As[lr][lc]     = aS[0];
        *(uint4*)&As[lr][lc + 8] = aS[1];
        __half2* bd = (__half2*)&Bs[lr][lc];
#pragma unroll
        for (int i = 0; i < 4; ++i) {
            bd[i * 2 + 0] = __floats2half2_rn(bS[i].x, bS[i].y);
            bd[i * 2 + 1] = __floats2half2_rn(bS[i].z, bS[i].w);
        }
    };

    fetch(0); stage(); __syncthreads();
    const int NKT = D_ / BK;   // 32
    for (int kt = 0; kt < NKT; ++kt) {
        const bool more = (kt + 1 < NKT);
        if (more) fetch((kt + 1) * BK);
        COMPUTE_TILE();
        __syncthreads();
        if (more) { stage(); __syncthreads(); }
    }

    const int gr = lane >> 2;
    const int gc = (lane & 3) * 2;
#pragma unroll
    for (int mt = 0; mt < 4; ++mt) {
#pragma unroll
        for (int h = 0; h < 2; ++h) {
            const int r = warp_m * 64 + mt * 16 + gr + h * 8;
            if (m0 + r < M) {
                const size_t rowbase = (size_t)(hb + m0 + r) * DF_;
#pragma unroll
                for (int nt = 0; nt < 4; ++nt) {
                    const int col = n0 + warp_n * 32 + nt * 8 + gc;
                    float v0 = acc[mt][nt][h * 2 + 0] + b1[e * DF_ + col];
                    float v1 = acc[mt][nt][h * 2 + 1] + b1[e * DF_ + col + 1];
                    v0 = gelu_exact(v0);
                    v1 = gelu_exact(v1);
                    *(__half2*)&g_h[rowbase + col] = __floats2half2_rn(v0, v1);
                }
            }
        }
    }
}

// ---------------- kernel 3: Y = H @ W2e^T + b2, scatter --------------------
__global__ __launch_bounds__(256) void gemm2_kernel(
    const float* __restrict__ W2, const float* __restrict__ b2,
    float* __restrict__ out) {
    const int e  = blockIdx.z;
    const int M  = g_cnt[e];
    const int m0 = blockIdx.x * BM;
    if (m0 >= M) return;
    const int n0 = blockIdx.y * BN;
    const int hb = g_off[e];

    __shared__ __half As[BM][BK + SKEW];
    __shared__ __half Bs[BN][BK + SKEW];

    const int tid = threadIdx.x;
    const int lane = tid & 31, wid = tid >> 5;
    const int warp_m = wid >> 2, warp_n = wid & 3;

    const int lr = tid >> 1;
    const int lc = (tid & 1) * 16;
    const int rg = m0 + lr;
    const bool rowok = (rg < M);
    const __half* aptr = nullptr;
    if (rowok) aptr = g_h + (size_t)(hb + rg) * DF_ + lc;
    const float* bptr = W2 + ((size_t)e * D_ + n0 + lr) * DF_ + lc;

    float acc[4][4][4];
#pragma unroll
    for (int i = 0; i < 4; ++i)
#pragma unroll
        for (int j = 0; j < 4; ++j)
#pragma unroll
            for (int k = 0; k < 4; ++k) acc[i][j][k] = 0.f;

    uint4 aS[2]; float4 bS[4];
    auto fetch = [&](int k0) {
        if (rowok) {
            aS[0] = *(const uint4*)(aptr + k0);
            aS[1] = *(const uint4*)(aptr + k0 + 8);
        } else {
            aS[0] = make_uint4(0, 0, 0, 0);
            aS[1] = make_uint4(0, 0, 0, 0);
        }
#pragma unroll
        for (int i = 0; i < 4; ++i) bS[i] = *(const float4*)(bptr + k0 + i * 4);
    };
    auto stage = [&]() {
        *(uint4*)&As[lr][lc]     = aS[0];
        *(uint4*)&As[lr][lc + 8] = aS[1];
        __half2* bd = (__half2*)&Bs[lr][lc];
#pragma unroll
        for (int i = 0; i < 4; ++i) {
            bd[i * 2 + 0] = __floats2half2_rn(bS[i].x, bS[i].y);
            bd[i * 2 + 1] = __floats2half2_rn(bS[i].z, bS[i].w);
        }
    };

    fetch(0); stage(); __syncthreads();
    const int NKT = DF_ / BK;  // 128
    for (int kt = 0; kt < NKT; ++kt) {
        const bool more = (kt + 1 < NKT);
        if (more) fetch((kt + 1) * BK);
        COMPUTE_TILE();
        __syncthreads();
        if (more) { stage(); __syncthreads(); }
    }

    const int gr = lane >> 2;
    const int gc = (lane & 3) * 2;
#pragma unroll
    for (int mt = 0; mt < 4; ++mt) {
#pragma unroll
        for (int h = 0; h < 2; ++h) {
            const int r = warp_m * 64 + mt * 16 + gr + h * 8;
            if (m0 + r < M) {
                const int   tok = g_tok[e * TMAX + m0 + r];
                const float w   = g_w[e * TMAX + m0 + r];
                float* orow = out + (size_t)tok * D_;
#pragma unroll
                for (int nt = 0; nt < 4; ++nt) {
                    const int col = n0 + warp_n * 32 + nt * 8 + gc;
                    const float v0 = acc[mt][nt][h * 2 + 0] + b2[e * D_ + col];
                    const float v1 = acc[mt][nt][h * 2 + 1] + b2[e * D_ + col + 1];
                    atomicAdd(&orow[col],     w * v0);
                    atomicAdd(&orow[col + 1], w * v1);
                }
            }
        }
    }
}

// ---------------- launch ----------------------------------------------------
extern "C" void kernel_launch(void* const* d_in, const int* in_sizes, int n_in,
                              void* d_out, int out_size) {
    const float* x     = (const float*)d_in[0];
    const float* gamma = (const float*)d_in[1];
    const float* beta  = (const float*)d_in[2];
    const float* Wg    = (const float*)d_in[3];
    const float* bg    = (const float*)d_in[4];
    const float* W1    = (const float*)d_in[5];
    const float* b1    = (const float*)d_in[6];
    const float* W2    = (const float*)d_in[7];
    const float* b2    = (const float*)d_in[8];
    float* out = (float*)d_out;

    const int T  = in_sizes[0] / D_;              // 4096 for B=2, S=2048
    const int mt = (T + BM - 1) / BM;             // 32

    reset_kernel<<<1, 32>>>();
    ln_gate_kernel<<<T, 256>>>(x, gamma, beta, Wg, bg, out);
    offsets_kernel<<<1, 32>>>();
    dim3 g1(mt, DF_ / BN, E_);                    // m fastest -> W1 L2 reuse
    gemm1_kernel<<<g1, 256>>>(W1, b1);
    dim3 g2(mt, D_ / BN, E_);
    gemm2_kernel<<<g2, 256>>>(W2, b2, out);
}